// round 4
// baseline (speedup 1.0000x reference)
#include <cuda_runtime.h>
#include <cuda_bf16.h>
#include <cstdint>

// SkipGramMultiContext: B=16384, C_MAX=10, K_NEG=5, DIM=128, VOCAB=100000
// Output: float32[2] = {positive_loss, negative_loss}
//
// Strategy: cp.async.bulk (async-proxy) row gathers into double-buffered SMEM,
// bypassing the LDG/L1tex in-flight-miss cap that pinned R1/R2 at ~2.8 TB/s.

#define B_SAMPLES 16384
#define C_MAX 10
#define K_NEG 5
#define DIM 128
#define NSCORE 15                       // 10 ctx + 5 neg
#define ROW_BYTES 512                   // 128 floats
#define ROWS_PER_SAMPLE 16              // 15 score rows + 1 target row
#define SAMPLE_BYTES (ROWS_PER_SAMPLE * ROW_BYTES)   // 8192
#define WARPS_PER_BLOCK 4
#define THREADS (WARPS_PER_BLOCK * 32)
#define NBUF 2
#define SMEM_BUF_BYTES (WARPS_PER_BLOCK * NBUF * SAMPLE_BYTES)    // 65536
#define SMEM_MBAR_OFF SMEM_BUF_BYTES
#define SMEM_TOTAL (SMEM_BUF_BYTES + WARPS_PER_BLOCK * NBUF * 8)  // + mbarriers
#define GRID_BLOCKS 444                 // 3 blocks/SM x 148 SMs

__device__ __forceinline__ uint32_t smem_u32(const void* p) {
    uint32_t a;
    asm("{ .reg .u64 t; cvta.to.shared.u64 t, %1; cvt.u32.u64 %0, t; }" : "=r"(a) : "l"(p));
    return a;
}

__device__ __forceinline__ void mbar_init(uint32_t mbar, uint32_t count) {
    asm volatile("mbarrier.init.shared.b64 [%0], %1;" :: "r"(mbar), "r"(count) : "memory");
}

__device__ __forceinline__ void mbar_expect_tx(uint32_t mbar, uint32_t bytes) {
    asm volatile("mbarrier.arrive.expect_tx.shared.b64 _, [%0], %1;"
                 :: "r"(mbar), "r"(bytes) : "memory");
}

__device__ __forceinline__ void mbar_wait(uint32_t mbar, uint32_t parity) {
    asm volatile(
        "{\n\t"
        ".reg .pred P;\n\t"
        "WAIT_%=: \n\t"
        "mbarrier.try_wait.parity.acquire.cta.shared::cta.b64 P, [%0], %1, 0x989680;\n\t"
        "@P bra.uni DONE_%=;\n\t"
        "bra.uni WAIT_%=;\n\t"
        "DONE_%=: \n\t"
        "}"
        :: "r"(mbar), "r"(parity) : "memory");
}

__device__ __forceinline__ void bulk_copy_g2s(uint32_t dst_smem, const void* src, uint32_t bytes,
                                              uint32_t mbar) {
    asm volatile(
        "cp.async.bulk.shared::cluster.global.mbarrier::complete_tx::bytes [%0], [%1], %2, [%3];"
        :: "r"(dst_smem), "l"(src), "r"(bytes), "r"(mbar) : "memory");
}

__device__ __forceinline__ void fence_proxy_async_cta() {
    asm volatile("fence.proxy.async.shared::cta;" ::: "memory");
}

__device__ __forceinline__ float neg_logsig(float x) {
    // -log(sigmoid(x)) = -min(x,0) + log(1 + exp(-|x|)); log arg in (1,2]
    return __logf(1.0f + __expf(-fabsf(x))) - fminf(x, 0.0f);
}

__device__ __forceinline__ float dot4(float4 a, float4 b) {
    return fmaf(a.x, b.x, fmaf(a.y, b.y, fmaf(a.z, b.z, a.w * b.w)));
}

// Multi-value tree reduce: after this, lanes 2r/2r+1 hold half-sums of v[r];
// caller adds shfl_xor(v[0], 1).
__device__ __forceinline__ void tree16(float v[16], int lane) {
    #pragma unroll
    for (int o = 16, nn = 8; o > 1; o >>= 1, nn >>= 1) {
        const bool up = (lane & o) != 0;
        #pragma unroll
        for (int i = 0; i < 8; i++) {
            if (i < nn) {
                const float send = up ? v[i] : v[i + nn];
                const float keep = up ? v[i + nn] : v[i];
                v[i] = keep + __shfl_xor_sync(0xffffffffu, send, o);
            }
        }
    }
}

// Lanes 0..15 issue one 512B bulk copy each (15 score rows + target row).
__device__ __forceinline__ void issue_sample(int s, uint32_t buf_smem, uint32_t mbar,
                                             const int* __restrict__ tw,
                                             const int* __restrict__ cw,
                                             const int* __restrict__ nw,
                                             const float* __restrict__ in_emb,
                                             const float* __restrict__ out_emb,
                                             int lane) {
    const float* src = in_emb;   // dummy init
    if (lane < C_MAX)
        src = out_emb + (size_t)__ldg(&cw[s * C_MAX + lane]) * DIM;
    else if (lane < NSCORE)
        src = out_emb + (size_t)__ldg(&nw[s * K_NEG + (lane - C_MAX)]) * DIM;
    else if (lane == NSCORE)
        src = in_emb + (size_t)__ldg(&tw[s]) * DIM;

    if (lane == 0) mbar_expect_tx(mbar, SAMPLE_BYTES);
    __syncwarp();
    if (lane < ROWS_PER_SAMPLE)
        bulk_copy_g2s(buf_smem + lane * ROW_BYTES, src, ROW_BYTES, mbar);
}

__global__ void zero_out_kernel(float* out) {
    if (threadIdx.x < 2) out[threadIdx.x] = 0.0f;
}

__global__ __launch_bounds__(THREADS)
void skipgram_loss_kernel(const int* __restrict__ tw,
                          const int* __restrict__ cw,
                          const int* __restrict__ cl,
                          const int* __restrict__ nw,
                          const float* __restrict__ in_emb,
                          const float* __restrict__ out_emb,
                          float* __restrict__ out) {
    extern __shared__ char smem[];
    const int lane = threadIdx.x & 31;
    const int wib  = threadIdx.x >> 5;
    const int wgid = blockIdx.x * WARPS_PER_BLOCK + wib;
    const int stride = GRID_BLOCKS * WARPS_PER_BLOCK;

    // This warp's two sample buffers + two mbarriers
    char* buf_ptr[NBUF];
    uint32_t buf_smem[NBUF], mbar[NBUF];
    #pragma unroll
    for (int b = 0; b < NBUF; b++) {
        buf_ptr[b]  = smem + (wib * NBUF + b) * SAMPLE_BYTES;
        buf_smem[b] = smem_u32(buf_ptr[b]);
        mbar[b]     = smem_u32(smem + SMEM_MBAR_OFF + (wib * NBUF + b) * 8);
    }

    if (lane == 0) {
        mbar_init(mbar[0], 1);
        mbar_init(mbar[1], 1);
    }
    __syncwarp();
    fence_proxy_async_cta();
    __syncthreads();   // harmless; keeps barrier init globally visible before any use

    // Prologue: pipeline 2 samples ahead
    if (wgid < B_SAMPLES)
        issue_sample(wgid, buf_smem[0], mbar[0], tw, cw, nw, in_emb, out_emb, lane);
    if (wgid + stride < B_SAMPLES)
        issue_sample(wgid + stride, buf_smem[1], mbar[1], tw, cw, nw, in_emb, out_emb, lane);

    float pos_acc = 0.0f, neg_acc = 0.0f;
    uint32_t phase[NBUF] = {0u, 0u};

    int i = 0;
    for (int s = wgid; s < B_SAMPLES; s += stride, i++) {
        const int b = i & 1;

        mbar_wait(mbar[b], phase[b]);
        phase[b] ^= 1u;

        const int len = __ldg(&cl[s]);   // uniform broadcast load

        // dots from smem
        const float4* row4 = reinterpret_cast<const float4*>(buf_ptr[b]);
        const float4 t4 = row4[NSCORE * 32 + lane];
        float v[16];
        #pragma unroll
        for (int r = 0; r < NSCORE; r++)
            v[r] = dot4(t4, row4[r * 32 + lane]);
        v[15] = 0.0f;

        tree16(v, lane);
        const float sc = v[0] + __shfl_xor_sync(0xffffffffu, v[0], 1);

        // even lane of each pair accumulates score r = (lane>>1)&15
        if ((lane & 1) == 0) {
            const int r = lane >> 1;
            if (r < C_MAX) {
                if (r < len) pos_acc += neg_logsig(sc) / (float)len;
            } else if (r < NSCORE) {
                if (len > 0) neg_acc += neg_logsig(-sc) * (1.0f / (float)K_NEG);
            }
        }

        // refill this buffer with the sample 2 steps ahead
        const int s2 = s + 2 * stride;
        if (s2 < B_SAMPLES) {
            __syncwarp();                 // all lanes finished reading buf b
            fence_proxy_async_cta();      // order generic reads before async writes
            issue_sample(s2, buf_smem[b], mbar[b], tw, cw, nw, in_emb, out_emb, lane);
        }
    }

    // final reduction: per-lane accumulators -> warp -> global
    #pragma unroll
    for (int o = 16; o > 0; o >>= 1) {
        pos_acc += __shfl_xor_sync(0xffffffffu, pos_acc, o);
        neg_acc += __shfl_xor_sync(0xffffffffu, neg_acc, o);
    }
    if (lane == 0) {
        const float invB = 1.0f / (float)B_SAMPLES;
        atomicAdd(&out[0], pos_acc * invB);
        atomicAdd(&out[1], neg_acc * invB);
    }
}

extern "C" void kernel_launch(void* const* d_in, const int* in_sizes, int n_in,
                              void* d_out, int out_size) {
    const int*   tw      = (const int*)d_in[0];
    const int*   cw      = (const int*)d_in[1];
    const int*   cl      = (const int*)d_in[2];
    const int*   nw      = (const int*)d_in[3];
    const float* in_emb  = (const float*)d_in[4];
    const float* out_emb = (const float*)d_in[5];
    float* out = (float*)d_out;

    zero_out_kernel<<<1, 32>>>(out);

    cudaFuncSetAttribute(skipgram_loss_kernel,
                         cudaFuncAttributeMaxDynamicSharedMemorySize, SMEM_TOTAL);
    skipgram_loss_kernel<<<GRID_BLOCKS, THREADS, SMEM_TOTAL>>>(
        tw, cw, cl, nw, in_emb, out_emb, out);
}

// round 5
// speedup vs baseline: 1.6989x; 1.6989x over previous
#include <cuda_runtime.h>
#include <cuda_bf16.h>
#include <cstdint>

// SkipGramMultiContext: B=16384, C_MAX=10, K_NEG=5, DIM=128, VOCAB=100000
// Output: float32[2] = {positive_loss, negative_loss}
//
// R1 winning structure (1 warp/sample, 16 front-batched LDG.128 gathers,
// 16-value tree reduction) + __ldcg on all row gathers to bypass L1
// allocation (L1 hit rate ~0 here; tests the L1tex outstanding-miss cap).

#define B_SAMPLES 16384
#define C_MAX 10
#define K_NEG 5
#define DIM 128
#define NSCORE (C_MAX + K_NEG)   // 15
#define WARPS_PER_BLOCK 8
#define THREADS (WARPS_PER_BLOCK * 32)

__device__ __forceinline__ float neg_logsig(float x) {
    // -log(sigmoid(x)) = -min(x,0) + log(1 + exp(-|x|)); log arg in (1,2]
    return __logf(1.0f + __expf(-fabsf(x))) - fminf(x, 0.0f);
}

__global__ void zero_out_kernel(float* out) {
    if (threadIdx.x < 2) out[threadIdx.x] = 0.0f;
}

__global__ __launch_bounds__(THREADS)
void skipgram_loss_kernel(const int* __restrict__ tw,
                          const int* __restrict__ cw,
                          const int* __restrict__ cl,
                          const int* __restrict__ nw,
                          const float* __restrict__ in_emb,
                          const float* __restrict__ out_emb,
                          float* __restrict__ out) {
    const int warp_id = (blockIdx.x * THREADS + threadIdx.x) >> 5;
    const int lane = threadIdx.x & 31;
    const int wib  = threadIdx.x >> 5;

    __shared__ float s_pos[WARPS_PER_BLOCK];
    __shared__ float s_neg[WARPS_PER_BLOCK];

    float pos_per = 0.0f, neg_per = 0.0f;

    if (warp_id < B_SAMPLES) {
        const int b = warp_id;

        // target row slice: lane holds 4 consecutive floats (LDG.128.CG)
        const int trow = __ldg(&tw[b]);
        const float4 t4 = __ldcg(reinterpret_cast<const float4*>(
            in_emb + (size_t)trow * DIM + lane * 4));

        // lanes 0..9 hold context indices, 10..14 negatives
        int idx = 0;
        if (lane < C_MAX)       idx = __ldg(&cw[b * C_MAX + lane]);
        else if (lane < NSCORE) idx = __ldg(&nw[b * K_NEG + (lane - C_MAX)]);
        const int len = __ldg(&cl[b]);

        // 15 coalesced row gathers (L1-bypassing), front-batched
        float v[16];
        #pragma unroll
        for (int r = 0; r < NSCORE; r++) {
            const int row = __shfl_sync(0xffffffffu, idx, r);
            const float4 w = __ldcg(reinterpret_cast<const float4*>(
                out_emb + (size_t)row * DIM + lane * 4));
            v[r] = fmaf(t4.x, w.x, fmaf(t4.y, w.y, fmaf(t4.z, w.z, t4.w * w.w)));
        }
        v[15] = 0.0f;

        // Multi-value tree reduction: 16 lane-sums in 16 shuffles.
        // After the loop + one o=1 finisher, lanes 2r and 2r+1 both hold the
        // full 32-lane sum of v[r]  (score index r = lane bits [4:1]).
        #pragma unroll
        for (int o = 16, nn = 8; o > 1; o >>= 1, nn >>= 1) {
            const bool up = (lane & o) != 0;
            #pragma unroll
            for (int i = 0; i < 8; i++) {
                if (i < nn) {
                    const float send  = up ? v[i] : v[i + nn];
                    const float keep  = up ? v[i + nn] : v[i];
                    v[i] = keep + __shfl_xor_sync(0xffffffffu, send, o);
                }
            }
        }
        v[0] += __shfl_xor_sync(0xffffffffu, v[0], 1);
        const float myscore = v[0];

        // even lane 2r evaluates score r; odd lanes contribute zero
        float pv = 0.0f, nv = 0.0f;
        if ((lane & 1) == 0) {
            const int r = lane >> 1;
            if (r < C_MAX) {
                if (r < len) pv = neg_logsig(myscore);
            } else if (r < NSCORE) {
                nv = neg_logsig(-myscore);
            }
        }

        #pragma unroll
        for (int o = 16; o > 0; o >>= 1) {
            pv += __shfl_xor_sync(0xffffffffu, pv, o);
            nv += __shfl_xor_sync(0xffffffffu, nv, o);
        }

        if (len > 0) {
            pos_per = pv / (float)len;
            neg_per = nv * (1.0f / (float)K_NEG);
        }
    }

    if (lane == 0) {
        s_pos[wib] = pos_per;
        s_neg[wib] = neg_per;
    }
    __syncthreads();

    if (threadIdx.x == 0) {
        float ps = 0.0f, ns = 0.0f;
        #pragma unroll
        for (int w = 0; w < WARPS_PER_BLOCK; w++) { ps += s_pos[w]; ns += s_neg[w]; }
        const float invB = 1.0f / (float)B_SAMPLES;
        atomicAdd(&out[0], ps * invB);
        atomicAdd(&out[1], ns * invB);
    }
}

extern "C" void kernel_launch(void* const* d_in, const int* in_sizes, int n_in,
                              void* d_out, int out_size) {
    const int*   tw      = (const int*)d_in[0];
    const int*   cw      = (const int*)d_in[1];
    const int*   cl      = (const int*)d_in[2];
    const int*   nw      = (const int*)d_in[3];
    const float* in_emb  = (const float*)d_in[4];
    const float* out_emb = (const float*)d_in[5];
    float* out = (float*)d_out;

    zero_out_kernel<<<1, 32>>>(out);

    const int num_blocks = B_SAMPLES / WARPS_PER_BLOCK;
    skipgram_loss_kernel<<<num_blocks, THREADS>>>(tw, cw, cl, nw, in_emb, out_emb, out);
}